// round 7
// baseline (speedup 1.0000x reference)
#include <cuda_runtime.h>
#include <cuda_fp16.h>
#include <cuda_fp8.h>
#include <cstdint>

// Fused gate_up GEMM + SiLU*mul + per-128-group fp8-e4m3 quant via legacy
// mma.sync (HMMA m16n8k16 fp16/fp32-acc). fp16 2-way split, W pre-scaled x64:
// gate_up*64 = x0w0 + x1w0 + x0w1 (dropped x1w1 ~2^-22). Epilogue descales.
//
// R6: 512 threads (4 warps/SMSP), warp tile 16x64, 4-stage cp.async ring
// (K=32/stage, SW64 64B rows), one __syncthreads per stage, RAW-spread MMAs.
//
// Output layout (float32): [T*I fp8-rounded values] ++ [T*(I/128) scales]

#define T_DIM 4096
#define H_DIM 4096
#define I_DIM 14336
#define NGROUPS (I_DIM / 128)

static const size_t XS_PLANE = (size_t)T_DIM * H_DIM;
static const size_t WS_PLANE = (size_t)2 * I_DIM * H_DIM;

__device__ __align__(16) __half g_xs[2ull * 4096ull * 4096ull];   //  64 MB
__device__ __align__(16) __half g_ws[2ull * 28672ull * 4096ull];  // 448 MB

// ---------------------------------------------------------------- pre-pass
__global__ __launch_bounds__(256)
void split_x_kernel(const float* __restrict__ src)
{
    const size_t n4 = XS_PLANE / 4;
    size_t i = (size_t)blockIdx.x * blockDim.x + threadIdx.x;
    const size_t stride = (size_t)gridDim.x * blockDim.x;
    for (; i < n4; i += stride) {
        float4 v = ((const float4*)src)[i];
        float f[4] = {v.x, v.y, v.z, v.w};
        __half h0[4], h1[4];
#pragma unroll
        for (int e = 0; e < 4; ++e) {
            h0[e] = __float2half_rn(f[e]);
            h1[e] = __float2half_rn(f[e] - __half2float(h0[e]));
        }
        ((__half2*)(g_xs))[i * 2]                = __halves2half2(h0[0], h0[1]);
        ((__half2*)(g_xs))[i * 2 + 1]            = __halves2half2(h0[2], h0[3]);
        ((__half2*)(g_xs + XS_PLANE))[i * 2]     = __halves2half2(h1[0], h1[1]);
        ((__half2*)(g_xs + XS_PLANE))[i * 2 + 1] = __halves2half2(h1[2], h1[3]);
    }
}

__global__ __launch_bounds__(256)
void split_w_kernel(const float* __restrict__ src)
{
    const size_t n4 = WS_PLANE / 4;
    size_t i = (size_t)blockIdx.x * blockDim.x + threadIdx.x;
    const size_t stride = (size_t)gridDim.x * blockDim.x;
    for (; i < n4; i += stride) {
        float4 v = ((const float4*)src)[i];
        float f[4] = {v.x * 64.0f, v.y * 64.0f, v.z * 64.0f, v.w * 64.0f};
        __half h0[4], h1[4];
#pragma unroll
        for (int e = 0; e < 4; ++e) {
            h0[e] = __float2half_rn(f[e]);
            h1[e] = __float2half_rn(f[e] - __half2float(h0[e]));
        }
        ((__half2*)(g_ws))[i * 2]                = __halves2half2(h0[0], h0[1]);
        ((__half2*)(g_ws))[i * 2 + 1]            = __halves2half2(h0[2], h0[3]);
        ((__half2*)(g_ws + WS_PLANE))[i * 2]     = __halves2half2(h1[0], h1[1]);
        ((__half2*)(g_ws + WS_PLANE))[i * 2 + 1] = __halves2half2(h1[2], h1[3]);
    }
}

// ---------------------------------------------------------------- main GEMM
// CTA: M=64 x N=256 (128 gate + 128 up), 16 warps in 4x4 -> warp tile 16x64.
// Stage (K=32): A0|A1 (64x64B each = 4KB) + B0|B1 (256x64B = 16KB each) = 40KB.
// 4 stages = 160KB.

#define STG      40960
#define A1_OFF   4096
#define B_OFF    8192
#define BP_OFF   16384
#define SMEM_SZ  (4 * STG)
#define YS       264

__device__ __forceinline__ uint32_t s2u(const void* p) {
    uint32_t a;
    asm("{ .reg .u64 t; cvta.to.shared.u64 t, %1; cvt.u32.u64 %0, t; }"
        : "=r"(a) : "l"(p));
    return a;
}
__device__ __forceinline__ void cp16(uint32_t s, const void* g) {
    asm volatile("cp.async.cg.shared.global [%0], [%1], 16;"
                 :: "r"(s), "l"(g) : "memory");
}
#define CP_COMMIT() asm volatile("cp.async.commit_group;" ::: "memory")
#define CP_WAIT2()  asm volatile("cp.async.wait_group 2;" ::: "memory")

__device__ __forceinline__ void ldsm4(uint32_t* r, uint32_t addr) {
    asm volatile("ldmatrix.sync.aligned.m8n8.x4.shared.b16 {%0,%1,%2,%3}, [%4];"
                 : "=r"(r[0]), "=r"(r[1]), "=r"(r[2]), "=r"(r[3]) : "r"(addr));
}
__device__ __forceinline__ void mma16816(float* c, const uint32_t* a,
                                         uint32_t b0, uint32_t b1) {
    asm volatile(
        "mma.sync.aligned.m16n8k16.row.col.f32.f16.f16.f32 "
        "{%0,%1,%2,%3}, {%4,%5,%6,%7}, {%8,%9}, {%0,%1,%2,%3};"
        : "+f"(c[0]), "+f"(c[1]), "+f"(c[2]), "+f"(c[3])
        : "r"(a[0]), "r"(a[1]), "r"(a[2]), "r"(a[3]), "r"(b0), "r"(b1));
}

__global__ __launch_bounds__(512, 1)
void mlp_mma_kernel(float* __restrict__ out)
{
    extern __shared__ __align__(1024) char smem[];
    const uint32_t sb = s2u(smem);
    const int tid = threadIdx.x;
    const int lane = tid & 31, wid = tid >> 5;
    const int wm = wid >> 2, wn = wid & 3;       // 4x4 warp grid
    const int row0 = blockIdx.x * 64;
    const int g0   = blockIdx.y * 128;

    // ---- producer: 5 x 16B chunks per thread per stage ----
    const int kc = tid & 3;                      // 16B chunk within 64B row
    const int arow = tid >> 2;                   // 0..127 (plane*64 + row)
    const int ap = arow >> 6, ar = arow & 63;

    const __half* gA = g_xs + (size_t)ap * XS_PLANE
                     + (size_t)(row0 + ar) * H_DIM + kc * 8;
    const uint32_t offA = (uint32_t)(ap * A1_OFF + ar * 64
                        + ((kc * 16) ^ ((ar & 6) << 3)));

    const __half* gB[4];
    uint32_t offB[4];
#pragma unroll
    for (int j = 0; j < 4; ++j) {
        int slot = j * 512 + tid;
        int bw = slot >> 2;                      // 0..511
        int bp = bw >> 8, n = bw & 255;
        size_t wr = (n < 128) ? (size_t)(g0 + n)
                              : (size_t)I_DIM + (size_t)g0 + (n - 128);
        gB[j] = g_ws + (size_t)bp * WS_PLANE + wr * H_DIM + kc * 8;
        offB[j] = (uint32_t)(B_OFF + bp * BP_OFF + n * 64
                + ((kc * 16) ^ ((n & 6) << 3)));
    }

    auto load_stage = [&](int s, int kt) {
        const uint32_t base = sb + s * STG;
        const int ko = kt * 32;
        cp16(base + offA, gA + ko);
#pragma unroll
        for (int j = 0; j < 4; ++j) cp16(base + offB[j], gB[j] + ko);
    };

    // ---- consumer fragment addressing (SW64, 64B rows) ----
    const uint32_t aAddr0 = (uint32_t)((wm * 16 + (lane & 15)) * 64);
    const uint32_t aCol0  = (uint32_t)((lane >> 4) * 16);
    const uint32_t aXor   = (uint32_t)((lane & 6) << 3);

    float acc[8][4];
#pragma unroll
    for (int j = 0; j < 8; ++j)
#pragma unroll
        for (int e = 0; e < 4; ++e) acc[j][e] = 0.0f;

    uint32_t bAddr0[4], bXor[4];
#pragma unroll
    for (int jj = 0; jj < 4; ++jj) {
        int nloc = wn * 64 + jj * 16 + (lane & 7) + ((lane & 16) >> 1);
        bAddr0[jj] = (uint32_t)(nloc * 64);
        bXor[jj]   = (uint32_t)((nloc & 6) << 3);
    }
    const uint32_t bCol0 = (uint32_t)(((lane >> 3) & 1) * 16);

    // prologue: stages 0..2
    load_stage(0, 0); CP_COMMIT();
    load_stage(1, 1); CP_COMMIT();
    load_stage(2, 2); CP_COMMIT();

    const int nK = H_DIM / 32;                   // 128 stages
    for (int kt = 0; kt < nK; ++kt) {
        CP_WAIT2();
        __syncthreads();
        if (kt + 3 < nK) load_stage((kt + 3) & 3, kt + 3);
        CP_COMMIT();

        const uint32_t sbase = sb + (kt & 3) * STG;
#pragma unroll
        for (int t = 0; t < 2; ++t) {
            uint32_t a0[4], a1[4];
            const uint32_t ac = (t * 32 + aCol0) ^ aXor;
            ldsm4(a0, sbase + aAddr0 + ac);
            ldsm4(a1, sbase + A1_OFF + aAddr0 + ac);
#pragma unroll
            for (int jj = 0; jj < 4; ++jj) {
                uint32_t b0[4], b1[4];
                const uint32_t bc = (t * 32 + bCol0) ^ bXor[jj];
                ldsm4(b0, sbase + B_OFF + bAddr0[jj] + bc);
                ldsm4(b1, sbase + B_OFF + BP_OFF + bAddr0[jj] + bc);
                float* c0 = acc[jj * 2];
                float* c1 = acc[jj * 2 + 1];
                mma16816(c0, a0, b0[0], b0[1]);   // x0*w0, n-half 0
                mma16816(c1, a0, b0[2], b0[3]);   // x0*w0, n-half 1
                mma16816(c0, a1, b0[0], b0[1]);   // x1*w0
                mma16816(c1, a1, b0[2], b0[3]);
                mma16816(c0, a0, b1[0], b1[1]);   // x0*w1
                mma16816(c1, a0, b1[2], b1[3]);
            }
        }
    }

    // ---- epilogue: stash descaled fp32, then silu*mul + fp8 quant ----
    __syncthreads();
    float* ys = (float*)smem;                    // 64 x YS (stages 0/1 dead)
    const float inv64 = 0.015625f;
    {
        const int R = wm * 16 + (lane >> 2);
#pragma unroll
        for (int j = 0; j < 8; ++j) {
            const int C = wn * 64 + (j >> 1) * 16 + (j & 1) * 8 + (lane & 3) * 2;
            ys[R * YS + C]           = acc[j][0] * inv64;
            ys[R * YS + C + 1]       = acc[j][1] * inv64;
            ys[(R + 8) * YS + C]     = acc[j][2] * inv64;
            ys[(R + 8) * YS + C + 1] = acc[j][3] * inv64;
        }
    }
    __syncthreads();

    float* res = out;
    float* scl = out + (size_t)T_DIM * I_DIM;
#pragma unroll
    for (int rr = 0; rr < 4; ++rr) {
        const int r = wid * 4 + rr;
        const int grow = row0 + r;
        const float* yr = ys + r * YS;
        const int c0 = lane * 4;

        float4 gv = *(const float4*)(yr + c0);
        float4 uv = *(const float4*)(yr + 128 + c0);
        float g4[4] = {gv.x, gv.y, gv.z, gv.w};
        float u4[4] = {uv.x, uv.y, uv.z, uv.w};
        float y[4];
#pragma unroll
        for (int e = 0; e < 4; ++e) {
            float g = g4[e];
            float sg = 1.0f / (1.0f + expf(-g));
            y[e] = g * sg * u4[e];
        }
        float m = fmaxf(fmaxf(fabsf(y[0]), fabsf(y[1])),
                        fmaxf(fabsf(y[2]), fabsf(y[3])));
#pragma unroll
        for (int off = 16; off > 0; off >>= 1)
            m = fmaxf(m, __shfl_xor_sync(0xffffffffu, m, off));
        float amax  = fmaxf(m, 1e-10f);
        float scale = __fdiv_rn(amax, 448.0f);

        float q[4];
#pragma unroll
        for (int e = 0; e < 4; ++e) {
            float qv = __fdiv_rn(y[e], scale);
            qv = fminf(fmaxf(qv, -448.0f), 448.0f);
            __nv_fp8_storage_t b =
                __nv_cvt_float_to_fp8(qv, __NV_SATFINITE, __NV_E4M3);
            __half_raw hr = __nv_cvt_fp8_to_halfraw(b, __NV_E4M3);
            q[e] = __half2float(__half(hr));
        }
        *(float4*)&res[(size_t)grow * I_DIM + g0 + c0] =
            make_float4(q[0], q[1], q[2], q[3]);
        if (lane == 0)
            scl[(size_t)grow * NGROUPS + blockIdx.y] = scale;
    }
}

// ---------------------------------------------------------------- launch
extern "C" void kernel_launch(void* const* d_in, const int* in_sizes, int n_in,
                              void* d_out, int out_size)
{
    const float* x = (const float*)d_in[0];
    const float* W = (const float*)d_in[1];
    float* out = (float*)d_out;

    split_x_kernel<<<4096, 256>>>(x);
    split_w_kernel<<<8192, 256>>>(W);

    cudaFuncSetAttribute(mlp_mma_kernel,
                         cudaFuncAttributeMaxDynamicSharedMemorySize, SMEM_SZ);
    dim3 grid(T_DIM / 64, I_DIM / 128);   // (64, 112)
    mlp_mma_kernel<<<grid, 512, SMEM_SZ>>>(out);
}

// round 8
// speedup vs baseline: 1.1521x; 1.1521x over previous
#include <cuda_runtime.h>
#include <cuda_fp16.h>
#include <cuda_fp8.h>
#include <cstdint>

// Fused gate_up GEMM + SiLU*mul + per-128-group fp8-e4m3 quant via mma.sync
// (HMMA m16n8k16 fp16/fp32-acc). fp16 2-way split, W pre-scaled x64:
// gate_up*64 = x0w0 + x1w0 + x0w1 (dropped x1w1 ~2^-22). Epilogue descales.
//
// R7: CTA 128x256, 8 warps (2x4), warp tile 64x64 -> smem fragment traffic
// (128KB + 48KB writes per K=32) < HMMA work (1536 cyc) => compute-bound.
// 4-stage cp.async ring, K=32/stage, SW64 64B rows.
//
// Output layout (float32): [T*I fp8-rounded values] ++ [T*(I/128) scales]

#define T_DIM 4096
#define H_DIM 4096
#define I_DIM 14336
#define NGROUPS (I_DIM / 128)

static const size_t XS_PLANE = (size_t)T_DIM * H_DIM;
static const size_t WS_PLANE = (size_t)2 * I_DIM * H_DIM;

__device__ __align__(16) __half g_xs[2ull * 4096ull * 4096ull];   //  64 MB
__device__ __align__(16) __half g_ws[2ull * 28672ull * 4096ull];  // 448 MB

// ---------------------------------------------------------------- pre-pass
__global__ __launch_bounds__(256)
void split_x_kernel(const float* __restrict__ src)
{
    const size_t n4 = XS_PLANE / 4;
    size_t i = (size_t)blockIdx.x * blockDim.x + threadIdx.x;
    const size_t stride = (size_t)gridDim.x * blockDim.x;
    for (; i < n4; i += stride) {
        float4 v = ((const float4*)src)[i];
        float f[4] = {v.x, v.y, v.z, v.w};
        __half h0[4], h1[4];
#pragma unroll
        for (int e = 0; e < 4; ++e) {
            h0[e] = __float2half_rn(f[e]);
            h1[e] = __float2half_rn(f[e] - __half2float(h0[e]));
        }
        ((__half2*)(g_xs))[i * 2]                = __halves2half2(h0[0], h0[1]);
        ((__half2*)(g_xs))[i * 2 + 1]            = __halves2half2(h0[2], h0[3]);
        ((__half2*)(g_xs + XS_PLANE))[i * 2]     = __halves2half2(h1[0], h1[1]);
        ((__half2*)(g_xs + XS_PLANE))[i * 2 + 1] = __halves2half2(h1[2], h1[3]);
    }
}

__global__ __launch_bounds__(256)
void split_w_kernel(const float* __restrict__ src)
{
    const size_t n4 = WS_PLANE / 4;
    size_t i = (size_t)blockIdx.x * blockDim.x + threadIdx.x;
    const size_t stride = (size_t)gridDim.x * blockDim.x;
    for (; i < n4; i += stride) {
        float4 v = ((const float4*)src)[i];
        float f[4] = {v.x * 64.0f, v.y * 64.0f, v.z * 64.0f, v.w * 64.0f};
        __half h0[4], h1[4];
#pragma unroll
        for (int e = 0; e < 4; ++e) {
            h0[e] = __float2half_rn(f[e]);
            h1[e] = __float2half_rn(f[e] - __half2float(h0[e]));
        }
        ((__half2*)(g_ws))[i * 2]                = __halves2half2(h0[0], h0[1]);
        ((__half2*)(g_ws))[i * 2 + 1]            = __halves2half2(h0[2], h0[3]);
        ((__half2*)(g_ws + WS_PLANE))[i * 2]     = __halves2half2(h1[0], h1[1]);
        ((__half2*)(g_ws + WS_PLANE))[i * 2 + 1] = __halves2half2(h1[2], h1[3]);
    }
}

// ---------------------------------------------------------------- main GEMM
// Stage (K=32): A0|A1 (128x64B = 8KB each) + B0|B1 (256x64B = 16KB each).
#define STG      49152
#define A1_OFF   8192
#define B_OFF    16384
#define BP_OFF   16384                // B1 = B_OFF + BP_OFF
#define SMEM_SZ  (4 * STG)            // 192 KB
#define YS       264

__device__ __forceinline__ uint32_t s2u(const void* p) {
    uint32_t a;
    asm("{ .reg .u64 t; cvta.to.shared.u64 t, %1; cvt.u32.u64 %0, t; }"
        : "=r"(a) : "l"(p));
    return a;
}
__device__ __forceinline__ void cp16(uint32_t s, const void* g) {
    asm volatile("cp.async.cg.shared.global [%0], [%1], 16;"
                 :: "r"(s), "l"(g) : "memory");
}
#define CP_COMMIT() asm volatile("cp.async.commit_group;" ::: "memory")
#define CP_WAIT2()  asm volatile("cp.async.wait_group 2;" ::: "memory")
#define CP_WAIT0()  asm volatile("cp.async.wait_group 0;" ::: "memory")

__device__ __forceinline__ void ldsm4(uint32_t* r, uint32_t addr) {
    asm volatile("ldmatrix.sync.aligned.m8n8.x4.shared.b16 {%0,%1,%2,%3}, [%4];"
                 : "=r"(r[0]), "=r"(r[1]), "=r"(r[2]), "=r"(r[3]) : "r"(addr));
}
__device__ __forceinline__ void mma16816(float* c, const uint32_t* a,
                                         uint32_t b0, uint32_t b1) {
    asm volatile(
        "mma.sync.aligned.m16n8k16.row.col.f32.f16.f16.f32 "
        "{%0,%1,%2,%3}, {%4,%5,%6,%7}, {%8,%9}, {%0,%1,%2,%3};"
        : "+f"(c[0]), "+f"(c[1]), "+f"(c[2]), "+f"(c[3])
        : "r"(a[0]), "r"(a[1]), "r"(a[2]), "r"(a[3]), "r"(b0), "r"(b1));
}

__global__ __launch_bounds__(256)
void mlp_mma_kernel(float* __restrict__ out)
{
    extern __shared__ __align__(1024) char smem[];
    const uint32_t sb = s2u(smem);
    const int tid = threadIdx.x;
    const int lane = tid & 31, wid = tid >> 5;
    const int wm = wid >> 2, wn = wid & 3;       // 2x4 warp grid
    const int row0 = blockIdx.x * 128;
    const int g0   = blockIdx.y * 128;

    // ---- producer: 12 x 16B chunks per thread per stage ----
    const int kc    = tid & 3;                   // 16B chunk within 64B row
    const int rowid = tid >> 2;                  // 0..63
    const uint32_t swx = (uint32_t)((kc * 16) ^ ((rowid & 6) << 3));

    const __half* gA0 = g_xs + (size_t)(row0 + rowid) * H_DIM + kc * 8;
    const __half* gA1 = gA0 + (size_t)64 * H_DIM;
    const uint32_t offA0 = (uint32_t)(rowid * 64) + swx;
    const uint32_t offA1 = (uint32_t)((rowid + 64) * 64) + swx;

    const __half* gB[4];
    uint32_t offB[4];
#pragma unroll
    for (int j = 0; j < 4; ++j) {
        int n = rowid + 64 * j;                  // 0..255
        size_t wr = (n < 128) ? (size_t)(g0 + n)
                              : (size_t)I_DIM + (size_t)g0 + (n - 128);
        gB[j]   = g_ws + wr * H_DIM + kc * 8;
        offB[j] = (uint32_t)(B_OFF + n * 64) + swx;
    }

    auto load_stage = [&](int s, int kt) {
        const uint32_t base = sb + s * STG;
        const int ko = kt * 32;
        cp16(base + offA0,          gA0 + ko);
        cp16(base + offA1,          gA1 + ko);
        cp16(base + A1_OFF + offA0, gA0 + XS_PLANE + ko);
        cp16(base + A1_OFF + offA1, gA1 + XS_PLANE + ko);
#pragma unroll
        for (int j = 0; j < 4; ++j) {
            cp16(base + offB[j],          gB[j] + ko);
            cp16(base + BP_OFF + offB[j], gB[j] + WS_PLANE + ko);
        }
    };

    // ---- consumer fragment addressing (SW64, 64B rows) ----
    const uint32_t aXor  = (uint32_t)((lane & 6) << 3);
    const uint32_t aCol0 = (uint32_t)((lane >> 4) * 16);
    uint32_t aAddr[4];
#pragma unroll
    for (int ms = 0; ms < 4; ++ms)
        aAddr[ms] = (uint32_t)((wm * 64 + ms * 16 + (lane & 15)) * 64);

    uint32_t bAddr[4];
#pragma unroll
    for (int jj = 0; jj < 4; ++jj) {
        int nloc = wn * 64 + jj * 16 + (lane & 7) + ((lane & 16) >> 1);
        bAddr[jj] = (uint32_t)(nloc * 64);
    }
    const uint32_t bCol0 = (uint32_t)(((lane >> 3) & 1) * 16);

    float acc[4][8][4];
#pragma unroll
    for (int ms = 0; ms < 4; ++ms)
#pragma unroll
        for (int j = 0; j < 8; ++j)
#pragma unroll
            for (int e = 0; e < 4; ++e) acc[ms][j][e] = 0.0f;

    load_stage(0, 0); CP_COMMIT();
    load_stage(1, 1); CP_COMMIT();
    load_stage(2, 2); CP_COMMIT();

    const int nK = H_DIM / 32;                   // 128 stages
    for (int kt = 0; kt < nK; ++kt) {
        CP_WAIT2();
        __syncthreads();
        if (kt + 3 < nK) load_stage((kt + 3) & 3, kt + 3);
        CP_COMMIT();

        const uint32_t sbase = sb + (kt & 3) * STG;
#pragma unroll
        for (int t = 0; t < 2; ++t) {
            uint32_t a0[4][4], a1[4][4];
            const uint32_t ac = (t * 32 + aCol0) ^ aXor;
#pragma unroll
            for (int ms = 0; ms < 4; ++ms) {
                ldsm4(a0[ms], sbase + aAddr[ms] + ac);
                ldsm4(a1[ms], sbase + A1_OFF + aAddr[ms] + ac);
            }
#pragma unroll
            for (int jj = 0; jj < 4; ++jj) {
                uint32_t b0[4], b1[4];
                const uint32_t bc = (t * 32 + bCol0) ^ aXor;
                ldsm4(b0, sbase + B_OFF + bAddr[jj] + bc);
                ldsm4(b1, sbase + B_OFF + BP_OFF + bAddr[jj] + bc);
                // term-major: same accumulator reuse distance = 8 MMAs
#pragma unroll
                for (int ms = 0; ms < 4; ++ms) {
                    mma16816(acc[ms][jj * 2],     a0[ms], b0[0], b0[1]);
                    mma16816(acc[ms][jj * 2 + 1], a0[ms], b0[2], b0[3]);
                }
#pragma unroll
                for (int ms = 0; ms < 4; ++ms) {
                    mma16816(acc[ms][jj * 2],     a1[ms], b0[0], b0[1]);
                    mma16816(acc[ms][jj * 2 + 1], a1[ms], b0[2], b0[3]);
                }
#pragma unroll
                for (int ms = 0; ms < 4; ++ms) {
                    mma16816(acc[ms][jj * 2],     a0[ms], b1[0], b1[1]);
                    mma16816(acc[ms][jj * 2 + 1], a0[ms], b1[2], b1[3]);
                }
            }
        }
    }

    // ---- epilogue: stash descaled fp32, then silu*mul + fp8 quant ----
    CP_WAIT0();
    __syncthreads();
    float* ys = (float*)smem;                    // 128 x YS floats (135 KB)
    const float inv64 = 0.015625f;
#pragma unroll
    for (int ms = 0; ms < 4; ++ms) {
        const int R = wm * 64 + ms * 16 + (lane >> 2);
#pragma unroll
        for (int j = 0; j < 8; ++j) {
            const int C = wn * 64 + (j >> 1) * 16 + (j & 1) * 8 + (lane & 3) * 2;
            ys[R * YS + C]           = acc[ms][j][0] * inv64;
            ys[R * YS + C + 1]       = acc[ms][j][1] * inv64;
            ys[(R + 8) * YS + C]     = acc[ms][j][2] * inv64;
            ys[(R + 8) * YS + C + 1] = acc[ms][j][3] * inv64;
        }
    }
    __syncthreads();

    float* res = out;
    float* scl = out + (size_t)T_DIM * I_DIM;
#pragma unroll
    for (int rr = 0; rr < 16; ++rr) {
        const int r = wid * 16 + rr;
        const int grow = row0 + r;
        const float* yr = ys + r * YS;
        const int c0 = lane * 4;

        float4 gv = *(const float4*)(yr + c0);
        float4 uv = *(const float4*)(yr + 128 + c0);
        float g4[4] = {gv.x, gv.y, gv.z, gv.w};
        float u4[4] = {uv.x, uv.y, uv.z, uv.w};
        float y[4];
#pragma unroll
        for (int e = 0; e < 4; ++e) {
            float g = g4[e];
            float sg = 1.0f / (1.0f + expf(-g));
            y[e] = g * sg * u4[e];
        }
        float m = fmaxf(fmaxf(fabsf(y[0]), fabsf(y[1])),
                        fmaxf(fabsf(y[2]), fabsf(y[3])));
#pragma unroll
        for (int off = 16; off > 0; off >>= 1)
            m = fmaxf(m, __shfl_xor_sync(0xffffffffu, m, off));
        float amax  = fmaxf(m, 1e-10f);
        float scale = __fdiv_rn(amax, 448.0f);

        float q[4];
#pragma unroll
        for (int e = 0; e < 4; ++e) {
            float qv = __fdiv_rn(y[e], scale);
            qv = fminf(fmaxf(qv, -448.0f), 448.0f);
            __nv_fp8_storage_t b =
                __nv_cvt_float_to_fp8(qv, __NV_SATFINITE, __NV_E4M3);
            __half_raw hr = __nv_cvt_fp8_to_halfraw(b, __NV_E4M3);
            q[e] = __half2float(__half(hr));
        }
        *(float4*)&res[(size_t)grow * I_DIM + g0 + c0] =
            make_float4(q[0], q[1], q[2], q[3]);
        if (lane == 0)
            scl[(size_t)grow * NGROUPS + blockIdx.y] = scale;
    }
}

// ---------------------------------------------------------------- launch
extern "C" void kernel_launch(void* const* d_in, const int* in_sizes, int n_in,
                              void* d_out, int out_size)
{
    const float* x = (const float*)d_in[0];
    const float* W = (const float*)d_in[1];
    float* out = (float*)d_out;

    split_x_kernel<<<4096, 256>>>(x);
    split_w_kernel<<<8192, 256>>>(W);

    cudaFuncSetAttribute(mlp_mma_kernel,
                         cudaFuncAttributeMaxDynamicSharedMemorySize, SMEM_SZ);
    dim3 grid(T_DIM / 128, I_DIM / 128);   // (32, 112)
    mlp_mma_kernel<<<grid, 256, SMEM_SZ>>>(out);
}